// round 5
// baseline (speedup 1.0000x reference)
#include <cuda_runtime.h>
#include <math.h>
#include <stdint.h>

#define N_NODES 10000
#define N_EDGES 320000
#define IN_F    256
#define HD      256   // N_HEADS * N_UNITS
#define NH      4
#define D1      64
#define OUTF    47
#define NEG     0.2f

// ---------------- scratch (no allocs allowed) ----------------
// NOTE: these are referenced ONLY from device code. Passing a __device__
// global as a kernel argument from host code silently passes the host shadow
// address (and GB300's ATS makes the write "succeed" into host memory) —
// that was the R1-R4 bug.
__device__ float g_feat1[N_NODES * HD];     // features @ W1
__device__ float g_h1   [N_NODES * HD];     // layer1 aggregation
__device__ float g_h2   [N_NODES * HD];     // elu(h1)
__device__ float g_el1  [N_NODES * NH];
__device__ float g_er1  [N_NODES * NH];
__device__ float g_feat2[N_NODES * OUTF];
__device__ float g_el2  [N_NODES];
__device__ float g_er2  [N_NODES];

// CSR (group edges by dst)
__device__ int   g_deg   [N_NODES];
__device__ int   g_rowptr[N_NODES + 1];
__device__ int   g_cursor[N_NODES];
__device__ int   g_esrc  [N_EDGES];
__device__ float g_ex1   [N_EDGES * NH];
__device__ float g_ex2   [N_EDGES];

// ---------------- init ----------------
__global__ void init_kernel() {
    int i = blockIdx.x * blockDim.x + threadIdx.x;
    int stride = gridDim.x * blockDim.x;
    for (int j = i; j < N_NODES; j += stride) { g_deg[j] = 0; g_cursor[j] = 0; }
}

// ---------------- CSR build ----------------
__global__ void count_kernel(const int* __restrict__ dst, int E) {
    int e = blockIdx.x * blockDim.x + threadIdx.x;
    if (e < E) atomicAdd(&g_deg[dst[e]], 1);
}

__global__ void scan_kernel() {
    __shared__ int sh[1024];
    __shared__ int carry_sh;
    int t = threadIdx.x;
    if (t == 0) carry_sh = 0;
    __syncthreads();
    for (int base = 0; base < N_NODES; base += 1024) {
        int idx = base + t;
        int v = (idx < N_NODES) ? g_deg[idx] : 0;
        sh[t] = v;
        __syncthreads();
        for (int off = 1; off < 1024; off <<= 1) {
            int add = (t >= off) ? sh[t - off] : 0;
            __syncthreads();
            sh[t] += add;
            __syncthreads();
        }
        int incl = sh[t];
        int carry = carry_sh;
        if (idx < N_NODES) g_rowptr[idx + 1] = carry + incl;
        __syncthreads();
        if (t == 1023) carry_sh = carry + incl;
        __syncthreads();
    }
    if (t == 0) g_rowptr[0] = 0;
}

__global__ void scatter_kernel(const int* __restrict__ src,
                               const int* __restrict__ dst, int E) {
    int e = blockIdx.x * blockDim.x + threadIdx.x;
    if (e >= E) return;
    int d = dst[e];
    int pos = atomicAdd(&g_cursor[d], 1);
    g_esrc[g_rowptr[d] + pos] = src[e];
}

// ---------------- GEMM1: g_feat1[N,256] = A[N,256] @ B[256,256] ----------------
// Output target is the device global, referenced in DEVICE code.
__global__ void gemm1_kernel(const float* __restrict__ A,
                             const float* __restrict__ B, int N) {
    const int K = IN_F, M = HD;
    __shared__ float As[16][65];
    __shared__ float Bs[16][65];
    int tid = threadIdx.x;
    int tx = tid & 15, ty = tid >> 4;
    int row0 = blockIdx.x * 64, col0 = blockIdx.y * 64;
    float acc[4][4] = {};

    for (int kk = 0; kk < K; kk += 16) {
#pragma unroll
        for (int i = 0; i < 4; i++) {
            int lin = tid + i * 256;
            int m = lin >> 4, k = lin & 15;
            int r = row0 + m;
            As[k][m] = (r < N) ? A[r * K + kk + k] : 0.f;
        }
#pragma unroll
        for (int i = 0; i < 4; i++) {
            int lin = tid + i * 256;
            int k = lin >> 6, n = lin & 63;
            Bs[k][n] = B[(kk + k) * M + col0 + n];
        }
        __syncthreads();
#pragma unroll
        for (int k = 0; k < 16; k++) {
            float a[4], b[4];
#pragma unroll
            for (int i = 0; i < 4; i++) a[i] = As[k][ty * 4 + i];
#pragma unroll
            for (int j = 0; j < 4; j++) b[j] = Bs[k][tx * 4 + j];
#pragma unroll
            for (int i = 0; i < 4; i++)
#pragma unroll
                for (int j = 0; j < 4; j++) acc[i][j] += a[i] * b[j];
        }
        __syncthreads();
    }
#pragma unroll
    for (int i = 0; i < 4; i++) {
        int r = row0 + ty * 4 + i;
        if (r < N)
#pragma unroll
            for (int j = 0; j < 4; j++)
                g_feat1[r * M + col0 + tx * 4 + j] = acc[i][j];
    }
}

// ---------------- attention dots layer1: el/er [N,4] ----------------
__global__ void attn1_kernel(const float* __restrict__ al,
                             const float* __restrict__ ar) {
    int n = blockIdx.x;
    int h = threadIdx.x >> 5;
    int lane = threadIdx.x & 31;
    const float* f = &g_feat1[n * HD + h * D1];
    float sl = 0.f, sr = 0.f;
    for (int d = lane; d < D1; d += 32) {
        float v = f[d];
        sl += v * al[h * D1 + d];
        sr += v * ar[h * D1 + d];
    }
#pragma unroll
    for (int o = 16; o; o >>= 1) {
        sl += __shfl_xor_sync(0xffffffffu, sl, o);
        sr += __shfl_xor_sync(0xffffffffu, sr, o);
    }
    if (lane == 0) {
        g_el1[n * NH + h] = sl;
        g_er1[n * NH + h] = sr;
    }
}

// ---------------- layer1 edge softmax (warp per (node, head)) ----------------
__global__ void softmax1_kernel() {
    int n = blockIdx.x;
    int h = threadIdx.x >> 5;
    int lane = threadIdx.x & 31;
    int r0 = g_rowptr[n];
    int deg = g_rowptr[n + 1] - r0;
    float ern = g_er1[n * NH + h];

    float mx = -INFINITY;
    for (int i = lane; i < deg; i += 32) {
        int s = g_esrc[r0 + i];
        float x = g_el1[s * NH + h] + ern;
        x = (x > 0.f) ? x : NEG * x;
        g_ex1[(r0 + i) * NH + h] = x;
        mx = fmaxf(mx, x);
    }
#pragma unroll
    for (int o = 16; o; o >>= 1)
        mx = fmaxf(mx, __shfl_xor_sync(0xffffffffu, mx, o));

    float den = 0.f;
    for (int i = lane; i < deg; i += 32) {
        float ex = expf(g_ex1[(r0 + i) * NH + h] - mx);
        g_ex1[(r0 + i) * NH + h] = ex;
        den += ex;
    }
#pragma unroll
    for (int o = 16; o; o >>= 1)
        den += __shfl_xor_sync(0xffffffffu, den, o);
    float dc = fmaxf(den, 1e-9f);

    for (int i = lane; i < deg; i += 32)
        g_ex1[(r0 + i) * NH + h] /= dc;
}

// ---------------- layer1 aggregation (gather, no atomics) ----------------
__global__ void agg1_kernel() {
    int n = blockIdx.x;
    int c = threadIdx.x;
    int h = c >> 6;
    int r0 = g_rowptr[n];
    int deg = g_rowptr[n + 1] - r0;
    float acc = 0.f;
    for (int i = 0; i < deg; i++) {
        int s = g_esrc[r0 + i];
        float a = g_ex1[(r0 + i) * NH + h];
        acc += a * g_feat1[s * HD + c];
    }
    g_h1[n * HD + c] = acc;
}

// ---------------- elu ----------------
__global__ void elu_kernel() {
    int i = blockIdx.x * blockDim.x + threadIdx.x;
    int stride = gridDim.x * blockDim.x;
    for (int j = i; j < N_NODES * HD; j += stride) {
        float x = g_h1[j];
        g_h2[j] = (x > 0.f) ? x : expm1f(x);
    }
}

// ---------------- layer2 GEMM + attention dots (block per node) ----------------
__global__ void layer2_node_kernel(const float* __restrict__ W2,
                                   const float* __restrict__ al2,
                                   const float* __restrict__ ar2) {
    int n = blockIdx.x;
    int t = threadIdx.x;          // 256
    __shared__ float sh[HD];
    __shared__ float red[4][OUTF];
    __shared__ float sl[OUTF], sr[OUTF];

    sh[t] = g_h2[n * HD + t];
    __syncthreads();

    if (t < 4 * OUTF) {
        int col = t % OUTF, part = t / OUTF;
        float acc = 0.f;
        int k0 = part * 64;
#pragma unroll 8
        for (int k = 0; k < 64; k++)
            acc += sh[k0 + k] * W2[(k0 + k) * OUTF + col];
        red[part][col] = acc;
    }
    __syncthreads();

    if (t < OUTF) {
        float f = red[0][t] + red[1][t] + red[2][t] + red[3][t];
        g_feat2[n * OUTF + t] = f;
        sl[t] = f * al2[t];
        sr[t] = f * ar2[t];
    }
    __syncthreads();

    if (t < 32) {
        float a = sl[t] + (t + 32 < OUTF ? sl[t + 32] : 0.f);
        float b = sr[t] + (t + 32 < OUTF ? sr[t + 32] : 0.f);
#pragma unroll
        for (int o = 16; o; o >>= 1) {
            a += __shfl_xor_sync(0xffffffffu, a, o);
            b += __shfl_xor_sync(0xffffffffu, b, o);
        }
        if (t == 0) { g_el2[n] = a; g_er2[n] = b; }
    }
}

// ---------------- layer2 edge softmax (warp per node) ----------------
__global__ void softmax2_kernel() {
    int warp = threadIdx.x >> 5;
    int lane = threadIdx.x & 31;
    int n = blockIdx.x * 4 + warp;
    if (n >= N_NODES) return;
    int r0 = g_rowptr[n];
    int deg = g_rowptr[n + 1] - r0;
    float ern = g_er2[n];

    float mx = -INFINITY;
    for (int i = lane; i < deg; i += 32) {
        int s = g_esrc[r0 + i];
        float x = g_el2[s] + ern;
        x = (x > 0.f) ? x : NEG * x;
        g_ex2[r0 + i] = x;
        mx = fmaxf(mx, x);
    }
#pragma unroll
    for (int o = 16; o; o >>= 1)
        mx = fmaxf(mx, __shfl_xor_sync(0xffffffffu, mx, o));

    float den = 0.f;
    for (int i = lane; i < deg; i += 32) {
        float ex = expf(g_ex2[r0 + i] - mx);
        g_ex2[r0 + i] = ex;
        den += ex;
    }
#pragma unroll
    for (int o = 16; o; o >>= 1)
        den += __shfl_xor_sync(0xffffffffu, den, o);
    float dc = fmaxf(den, 1e-9f);

    for (int i = lane; i < deg; i += 32)
        g_ex2[r0 + i] /= dc;
}

// ---------------- layer2 aggregation fused with log_softmax ----------------
__global__ void agg2_ls_kernel(float* __restrict__ out) {
    int warp = threadIdx.x >> 5;
    int lane = threadIdx.x & 31;
    int n = blockIdx.x * 4 + warp;
    if (n >= N_NODES) return;
    int r0 = g_rowptr[n];
    int deg = g_rowptr[n + 1] - r0;
    bool hi = (lane + 32) < OUTF;

    float a0 = 0.f, a1 = 0.f;
    for (int i = 0; i < deg; i++) {
        int s = g_esrc[r0 + i];
        float w = g_ex2[r0 + i];
        a0 += w * g_feat2[s * OUTF + lane];
        if (hi) a1 += w * g_feat2[s * OUTF + lane + 32];
    }

    float v0 = a0;
    float v1 = hi ? a1 : -INFINITY;
    float mx = fmaxf(v0, v1);
#pragma unroll
    for (int o = 16; o; o >>= 1)
        mx = fmaxf(mx, __shfl_xor_sync(0xffffffffu, mx, o));
    float s_ = expf(v0 - mx) + (hi ? expf(v1 - mx) : 0.f);
#pragma unroll
    for (int o = 16; o; o >>= 1)
        s_ += __shfl_xor_sync(0xffffffffu, s_, o);
    float ls = logf(s_) + mx;
    out[n * OUTF + lane] = v0 - ls;
    if (hi) out[n * OUTF + lane + 32] = v1 - ls;
}

// ---------------- launch ----------------
extern "C" void kernel_launch(void* const* d_in, const int* in_sizes, int n_in,
                              void* d_out, int out_size) {
    const float* features = (const float*)d_in[0];
    const int*   src      = (const int*)d_in[1];
    const int*   dst      = (const int*)d_in[2];
    const float* W1       = (const float*)d_in[3];
    const float* al1      = (const float*)d_in[4];
    const float* ar1      = (const float*)d_in[5];
    const float* W2       = (const float*)d_in[6];
    const float* al2      = (const float*)d_in[7];
    const float* ar2      = (const float*)d_in[8];
    float* out = (float*)d_out;

    int N = in_sizes[0] / IN_F;   // 10000
    int E = in_sizes[1];          // 320000
    if (N > N_NODES) N = N_NODES;
    if (E > N_EDGES) E = N_EDGES;

    // CSR build (group by dst)
    init_kernel<<<80, 256>>>();
    count_kernel<<<(E + 255) / 256, 256>>>(dst, E);
    scan_kernel<<<1, 1024>>>();
    scatter_kernel<<<(E + 255) / 256, 256>>>(src, dst, E);

    // layer 1
    dim3 g1((N + 63) / 64, HD / 64);
    gemm1_kernel<<<g1, 256>>>(features, W1, N);
    attn1_kernel<<<N, 128>>>(al1, ar1);
    softmax1_kernel<<<N, 128>>>();
    agg1_kernel<<<N, 256>>>();
    elu_kernel<<<1024, 256>>>();

    // layer 2
    layer2_node_kernel<<<N, 256>>>(W2, al2, ar2);
    softmax2_kernel<<<(N + 3) / 4, 128>>>();
    agg2_ls_kernel<<<(N + 3) / 4, 128>>>(out);
}

// round 6
// speedup vs baseline: 1.1502x; 1.1502x over previous
#include <cuda_runtime.h>
#include <math.h>
#include <stdint.h>

#define N_NODES 10000
#define N_EDGES 320000
#define IN_F    256
#define HD      256   // N_HEADS * N_UNITS
#define NH      4
#define D1      64
#define OUTF    47
#define NEG     0.2f

// ---------------- scratch (device-code references ONLY; passing a __device__
// symbol as a host-side kernel arg silently uses the host shadow: R1-R4 bug) --
__device__ float g_feat1[N_NODES * HD];
__device__ float g_h2   [N_NODES * HD];
__device__ float g_el1  [N_NODES * NH];
__device__ float g_er1  [N_NODES * NH];
__device__ float g_feat2[N_NODES * OUTF];
__device__ float g_el2  [N_NODES];
__device__ float g_er2  [N_NODES];

__device__ int   g_deg   [N_NODES];
__device__ int   g_rowptr[N_NODES + 1];
__device__ int   g_cursor[N_NODES];
__device__ int   g_esrc  [N_EDGES];
__device__ float g_ex1   [N_EDGES * NH];

// ---------------- init ----------------
__global__ void init_kernel() {
    int i = blockIdx.x * blockDim.x + threadIdx.x;
    int stride = gridDim.x * blockDim.x;
    for (int j = i; j < N_NODES; j += stride) { g_deg[j] = 0; g_cursor[j] = 0; }
}

// ---------------- CSR build ----------------
__global__ void count_kernel(const int* __restrict__ dst, int E) {
    int e = blockIdx.x * blockDim.x + threadIdx.x;
    if (e < E) atomicAdd(&g_deg[dst[e]], 1);
}

// fast single-block scan: each thread owns 10 consecutive elements
__global__ void scan_kernel() {
    __shared__ int part[1024];
    const int PER = (N_NODES + 1023) / 1024;   // 10
    int t = threadIdx.x;
    int base = t * PER;
    int loc[PER];
    int sum = 0;
#pragma unroll
    for (int i = 0; i < PER; i++) {
        int idx = base + i;
        int v = (idx < N_NODES) ? g_deg[idx] : 0;
        sum += v;
        loc[i] = sum;                          // inclusive within chunk
    }
    part[t] = sum;
    __syncthreads();
    for (int off = 1; off < 1024; off <<= 1) {
        int add = (t >= off) ? part[t - off] : 0;
        __syncthreads();
        part[t] += add;
        __syncthreads();
    }
    int offset = (t > 0) ? part[t - 1] : 0;
#pragma unroll
    for (int i = 0; i < PER; i++) {
        int idx = base + i;
        if (idx < N_NODES) g_rowptr[idx + 1] = offset + loc[i];
    }
    if (t == 0) g_rowptr[0] = 0;
}

__global__ void scatter_kernel(const int* __restrict__ src,
                               const int* __restrict__ dst, int E) {
    int e = blockIdx.x * blockDim.x + threadIdx.x;
    if (e >= E) return;
    int d = dst[e];
    int pos = atomicAdd(&g_cursor[d], 1);
    g_esrc[g_rowptr[d] + pos] = src[e];
}

// ---------------- GEMM1 + attention dots fused ----------------
// g_feat1[N,256] = A[N,256] @ B[256,256]; blockIdx.y = head (64 cols = 1 head)
// epilogue computes el/er dots for this head via width-16 shuffle reduction.
__global__ void gemm1_attn_kernel(const float* __restrict__ A,
                                  const float* __restrict__ B,
                                  const float* __restrict__ al,
                                  const float* __restrict__ ar, int N) {
    __shared__ float As[16][132];   // [k][m], 128 rows
    __shared__ float Bs[16][68];    // [k][n], 64 cols
    int tid = threadIdx.x;          // 256
    int tx = tid & 15, ty = tid >> 4;
    int h = blockIdx.y;
    int row0 = blockIdx.x * 128;
    int col0 = h * 64;
    float acc[8][4] = {};

    for (int kk = 0; kk < IN_F; kk += 16) {
#pragma unroll
        for (int i = 0; i < 2; i++) {
            int idx = tid + i * 256;            // 0..511
            int m = idx >> 2, k4 = (idx & 3) * 4;
            int r = row0 + m;
            float4 v = (r < N) ? *(const float4*)&A[r * IN_F + kk + k4]
                               : make_float4(0.f, 0.f, 0.f, 0.f);
            As[k4 + 0][m] = v.x; As[k4 + 1][m] = v.y;
            As[k4 + 2][m] = v.z; As[k4 + 3][m] = v.w;
        }
        {
            int k = tid >> 4, n4 = (tid & 15) * 4;
            *(float4*)&Bs[k][n4] = *(const float4*)&B[(kk + k) * HD + col0 + n4];
        }
        __syncthreads();
#pragma unroll
        for (int k = 0; k < 16; k++) {
            float a[8], b[4];
#pragma unroll
            for (int i = 0; i < 8; i++) a[i] = As[k][ty * 8 + i];
#pragma unroll
            for (int j = 0; j < 4; j++) b[j] = Bs[k][tx * 4 + j];
#pragma unroll
            for (int i = 0; i < 8; i++)
#pragma unroll
                for (int j = 0; j < 4; j++) acc[i][j] += a[i] * b[j];
        }
        __syncthreads();
    }

    float alv[4], arv[4];
#pragma unroll
    for (int j = 0; j < 4; j++) {
        alv[j] = al[h * D1 + tx * 4 + j];
        arv[j] = ar[h * D1 + tx * 4 + j];
    }
#pragma unroll
    for (int i = 0; i < 8; i++) {
        int r = row0 + ty * 8 + i;
        if (r < N) {
            float4 v = make_float4(acc[i][0], acc[i][1], acc[i][2], acc[i][3]);
            *(float4*)&g_feat1[r * HD + col0 + tx * 4] = v;
        }
        float el = acc[i][0]*alv[0] + acc[i][1]*alv[1] + acc[i][2]*alv[2] + acc[i][3]*alv[3];
        float er = acc[i][0]*arv[0] + acc[i][1]*arv[1] + acc[i][2]*arv[2] + acc[i][3]*arv[3];
#pragma unroll
        for (int o = 8; o; o >>= 1) {
            el += __shfl_xor_sync(0xffffffffu, el, o, 16);
            er += __shfl_xor_sync(0xffffffffu, er, o, 16);
        }
        if (tx == 0 && r < N) {
            g_el1[r * NH + h] = el;
            g_er1[r * NH + h] = er;
        }
    }
}

// ---------------- layer1: edge softmax + aggregation + elu (fused) ----------
// block per node, 256 threads. Warps 0-3: per-head softmax (un-normalized ex
// stored to g_ex1, denom to smem). Then all threads gather; divide at the end.
__global__ void sfm_agg1_kernel() {
    int n = blockIdx.x;
    int tid = threadIdx.x;
    int wid = tid >> 5, lane = tid & 31;
    __shared__ float den_sh[NH];
    int r0 = g_rowptr[n];
    int deg = g_rowptr[n + 1] - r0;

    if (wid < NH) {
        int h = wid;
        float ern = g_er1[n * NH + h];
        float mx = -INFINITY;
        for (int i = lane; i < deg; i += 32) {
            int s = g_esrc[r0 + i];
            float x = g_el1[s * NH + h] + ern;
            x = (x > 0.f) ? x : NEG * x;
            g_ex1[(r0 + i) * NH + h] = x;
            mx = fmaxf(mx, x);
        }
#pragma unroll
        for (int o = 16; o; o >>= 1)
            mx = fmaxf(mx, __shfl_xor_sync(0xffffffffu, mx, o));
        float den = 0.f;
        for (int i = lane; i < deg; i += 32) {
            float ex = expf(g_ex1[(r0 + i) * NH + h] - mx);
            g_ex1[(r0 + i) * NH + h] = ex;
            den += ex;
        }
#pragma unroll
        for (int o = 16; o; o >>= 1)
            den += __shfl_xor_sync(0xffffffffu, den, o);
        if (lane == 0) den_sh[h] = fmaxf(den, 1e-9f);
    }
    __syncthreads();

    int c = tid;
    int h = c >> 6;
    float acc = 0.f;
    for (int i = 0; i < deg; i++) {
        int s = g_esrc[r0 + i];
        acc += g_ex1[(r0 + i) * NH + h] * g_feat1[s * HD + c];
    }
    acc /= den_sh[h];
    g_h2[n * HD + c] = (acc > 0.f) ? acc : expm1f(acc);   // elu fused
}

// ---------------- layer2 GEMM + attention dots (block per node) --------------
__global__ void layer2_node_kernel(const float* __restrict__ W2,
                                   const float* __restrict__ al2,
                                   const float* __restrict__ ar2) {
    int n = blockIdx.x;
    int t = threadIdx.x;          // 256
    __shared__ float sh[HD];
    __shared__ float red[4][OUTF];
    __shared__ float sl[OUTF], sr[OUTF];

    sh[t] = g_h2[n * HD + t];
    __syncthreads();

    if (t < 4 * OUTF) {
        int col = t % OUTF, part = t / OUTF;
        float acc = 0.f;
        int k0 = part * 64;
#pragma unroll 8
        for (int k = 0; k < 64; k++)
            acc += sh[k0 + k] * W2[(k0 + k) * OUTF + col];
        red[part][col] = acc;
    }
    __syncthreads();

    if (t < OUTF) {
        float f = red[0][t] + red[1][t] + red[2][t] + red[3][t];
        g_feat2[n * OUTF + t] = f;
        sl[t] = f * al2[t];
        sr[t] = f * ar2[t];
    }
    __syncthreads();

    if (t < 32) {
        float a = sl[t] + (t + 32 < OUTF ? sl[t + 32] : 0.f);
        float b = sr[t] + (t + 32 < OUTF ? sr[t + 32] : 0.f);
#pragma unroll
        for (int o = 16; o; o >>= 1) {
            a += __shfl_xor_sync(0xffffffffu, a, o);
            b += __shfl_xor_sync(0xffffffffu, b, o);
        }
        if (t == 0) { g_el2[n] = a; g_er2[n] = b; }
    }
}

// ---------------- layer2: softmax + aggregation + log_softmax (fused) -------
// warp per node. exp recomputed in gather pass (broadcast reads) — no g_ex2.
__global__ void agg2_ls_kernel(float* __restrict__ out, int N) {
    int warp = threadIdx.x >> 5;
    int lane = threadIdx.x & 31;
    int n = blockIdx.x * 4 + warp;
    if (n >= N) return;
    int r0 = g_rowptr[n];
    int deg = g_rowptr[n + 1] - r0;
    float ern = g_er2[n];

    float mx = -INFINITY;
    for (int i = lane; i < deg; i += 32) {
        int s = g_esrc[r0 + i];
        float x = g_el2[s] + ern;
        x = (x > 0.f) ? x : NEG * x;
        mx = fmaxf(mx, x);
    }
#pragma unroll
    for (int o = 16; o; o >>= 1)
        mx = fmaxf(mx, __shfl_xor_sync(0xffffffffu, mx, o));

    float den = 0.f;
    for (int i = lane; i < deg; i += 32) {
        int s = g_esrc[r0 + i];
        float x = g_el2[s] + ern;
        x = (x > 0.f) ? x : NEG * x;
        den += expf(x - mx);
    }
#pragma unroll
    for (int o = 16; o; o >>= 1)
        den += __shfl_xor_sync(0xffffffffu, den, o);
    den = fmaxf(den, 1e-9f);

    bool hi = (lane + 32) < OUTF;
    float a0 = 0.f, a1 = 0.f;
    for (int i = 0; i < deg; i++) {
        int s = g_esrc[r0 + i];
        float x = g_el2[s] + ern;             // broadcast: same addr all lanes
        x = (x > 0.f) ? x : NEG * x;
        float w = expf(x - mx);
        a0 += w * g_feat2[s * OUTF + lane];
        if (hi) a1 += w * g_feat2[s * OUTF + lane + 32];
    }
    a0 /= den;
    a1 /= den;

    float v0 = a0;
    float v1 = hi ? a1 : -INFINITY;
    float m2 = fmaxf(v0, v1);
#pragma unroll
    for (int o = 16; o; o >>= 1)
        m2 = fmaxf(m2, __shfl_xor_sync(0xffffffffu, m2, o));
    float s_ = expf(v0 - m2) + (hi ? expf(v1 - m2) : 0.f);
#pragma unroll
    for (int o = 16; o; o >>= 1)
        s_ += __shfl_xor_sync(0xffffffffu, s_, o);
    float ls = logf(s_) + m2;
    out[n * OUTF + lane] = v0 - ls;
    if (hi) out[n * OUTF + lane + 32] = v1 - ls;
}

// ---------------- launch ----------------
extern "C" void kernel_launch(void* const* d_in, const int* in_sizes, int n_in,
                              void* d_out, int out_size) {
    const float* features = (const float*)d_in[0];
    const int*   src      = (const int*)d_in[1];
    const int*   dst      = (const int*)d_in[2];
    const float* W1       = (const float*)d_in[3];
    const float* al1      = (const float*)d_in[4];
    const float* ar1      = (const float*)d_in[5];
    const float* W2       = (const float*)d_in[6];
    const float* al2      = (const float*)d_in[7];
    const float* ar2      = (const float*)d_in[8];
    float* out = (float*)d_out;

    int N = in_sizes[0] / IN_F;   // 10000
    int E = in_sizes[1];          // 320000
    if (N > N_NODES) N = N_NODES;
    if (E > N_EDGES) E = N_EDGES;

    // CSR build (group by dst)
    init_kernel<<<20, 1024>>>();
    count_kernel<<<(E + 255) / 256, 256>>>(dst, E);
    scan_kernel<<<1, 1024>>>();
    scatter_kernel<<<(E + 255) / 256, 256>>>(src, dst, E);

    // layer 1
    dim3 g1((N + 127) / 128, NH);
    gemm1_attn_kernel<<<g1, 256>>>(features, W1, al1, ar1, N);
    sfm_agg1_kernel<<<N, 256>>>();

    // layer 2
    layer2_node_kernel<<<N, 256>>>(W2, al2, ar2);
    agg2_ls_kernel<<<(N + 3) / 4, 128>>>(out, N);
}

// round 7
// speedup vs baseline: 1.4406x; 1.2525x over previous
#include <cuda_runtime.h>
#include <math.h>
#include <stdint.h>

#define N_NODES 10000
#define N_EDGES 320000
#define IN_F    256
#define HD      256   // N_HEADS * N_UNITS
#define NH      4
#define D1      64
#define OUTF    47
#define NEG     0.2f

// ---------------- scratch (device-code references ONLY) ----------------
__device__ float g_feat1[N_NODES * HD];
__device__ float g_h2   [N_NODES * HD];
__device__ float g_el1  [N_NODES * NH];
__device__ float g_er1  [N_NODES * NH];
__device__ float g_feat2[N_NODES * OUTF];
__device__ float g_el2  [N_NODES];
__device__ float g_er2  [N_NODES];

__device__ int   g_deg   [N_NODES];
__device__ int   g_rowptr[N_NODES + 1];
__device__ int   g_cursor[N_NODES];
__device__ int   g_esrc  [N_EDGES];

__device__ __forceinline__ float tf32r(float x) {
    uint32_t u;
    asm("cvt.rna.tf32.f32 %0, %1;" : "=r"(u) : "f"(x));
    return __uint_as_float(u);
}

// ---------------- init ----------------
__global__ void init_kernel() {
    int i = blockIdx.x * blockDim.x + threadIdx.x;
    int stride = gridDim.x * blockDim.x;
    for (int j = i; j < N_NODES; j += stride) { g_deg[j] = 0; g_cursor[j] = 0; }
}

// ---------------- CSR build ----------------
__global__ void count_kernel(const int* __restrict__ dst, int E) {
    int e = blockIdx.x * blockDim.x + threadIdx.x;
    if (e < E) atomicAdd(&g_deg[dst[e]], 1);
}

__global__ void scan_kernel() {
    __shared__ int part[1024];
    const int PER = (N_NODES + 1023) / 1024;   // 10
    int t = threadIdx.x;
    int base = t * PER;
    int loc[PER];
    int sum = 0;
#pragma unroll
    for (int i = 0; i < PER; i++) {
        int idx = base + i;
        int v = (idx < N_NODES) ? g_deg[idx] : 0;
        sum += v;
        loc[i] = sum;
    }
    part[t] = sum;
    __syncthreads();
    for (int off = 1; off < 1024; off <<= 1) {
        int add = (t >= off) ? part[t - off] : 0;
        __syncthreads();
        part[t] += add;
        __syncthreads();
    }
    int offset = (t > 0) ? part[t - 1] : 0;
#pragma unroll
    for (int i = 0; i < PER; i++) {
        int idx = base + i;
        if (idx < N_NODES) g_rowptr[idx + 1] = offset + loc[i];
    }
    if (t == 0) g_rowptr[0] = 0;
}

__global__ void scatter_kernel(const int* __restrict__ src,
                               const int* __restrict__ dst, int E) {
    int e = blockIdx.x * blockDim.x + threadIdx.x;
    if (e >= E) return;
    int d = dst[e];
    int pos = atomicAdd(&g_cursor[d], 1);
    g_esrc[g_rowptr[d] + pos] = src[e];
}

// ---------------- GEMM1 (tf32 mma.sync) + attention dots fused --------------
// block tile 128(M) x 64(N=one head), BK=32; 8 warps as 4(M) x 2(N).
// warp tile 32x32 = 2 m16-frags x 4 n8-frags, mma.m16n8k8.tf32.
__global__ void gemm1_attn_kernel(const float* __restrict__ A,
                                  const float* __restrict__ B,
                                  const float* __restrict__ al,
                                  const float* __restrict__ ar, int N) {
    __shared__ float As[128][36];   // [m][k], stride 36: (4g+tig) distinct mod 32
    __shared__ float Bs[32][72];    // [k][n], stride 72: (8tig+g) distinct mod 32
    __shared__ float el_sh[128], er_sh[128];

    int tid  = threadIdx.x;
    int wid  = tid >> 5, lane = tid & 31;
    int g    = lane >> 2, tig = lane & 3;
    int warpM = wid >> 1, warpN = wid & 1;
    int h    = blockIdx.y;
    int row0 = blockIdx.x * 128, col0 = h * 64;

    if (tid < 128) { el_sh[tid] = 0.f; er_sh[tid] = 0.f; }

    float c[2][4][4];
#pragma unroll
    for (int mf = 0; mf < 2; mf++)
#pragma unroll
        for (int nf = 0; nf < 4; nf++)
#pragma unroll
            for (int j = 0; j < 4; j++) c[mf][nf][j] = 0.f;

    for (int kk = 0; kk < IN_F; kk += 32) {
        // A tile: 128x32 = 1024 float4 loads over 256 threads
#pragma unroll
        for (int i = 0; i < 4; i++) {
            int idx = tid + i * 256;
            int m = idx >> 3, kq = (idx & 7) * 4;
            int r = row0 + m;
            float4 v = (r < N) ? *(const float4*)&A[r * IN_F + kk + kq]
                               : make_float4(0.f, 0.f, 0.f, 0.f);
            As[m][kq + 0] = tf32r(v.x); As[m][kq + 1] = tf32r(v.y);
            As[m][kq + 2] = tf32r(v.z); As[m][kq + 3] = tf32r(v.w);
        }
        // B tile: 32x64 = 512 float4 loads
#pragma unroll
        for (int i = 0; i < 2; i++) {
            int idx = tid + i * 256;
            int k = idx >> 4, nq = (idx & 15) * 4;
            float4 v = *(const float4*)&B[(kk + k) * HD + col0 + nq];
            Bs[k][nq + 0] = tf32r(v.x); Bs[k][nq + 1] = tf32r(v.y);
            Bs[k][nq + 2] = tf32r(v.z); Bs[k][nq + 3] = tf32r(v.w);
        }
        __syncthreads();

#pragma unroll
        for (int ks = 0; ks < 32; ks += 8) {
            uint32_t af[2][4], bf[4][2];
#pragma unroll
            for (int mf = 0; mf < 2; mf++) {
                int mbase = warpM * 32 + mf * 16;
                af[mf][0] = __float_as_uint(As[mbase + g    ][ks + tig    ]);
                af[mf][1] = __float_as_uint(As[mbase + g + 8][ks + tig    ]);
                af[mf][2] = __float_as_uint(As[mbase + g    ][ks + tig + 4]);
                af[mf][3] = __float_as_uint(As[mbase + g + 8][ks + tig + 4]);
            }
#pragma unroll
            for (int nf = 0; nf < 4; nf++) {
                int nbase = warpN * 32 + nf * 8;
                bf[nf][0] = __float_as_uint(Bs[ks + tig    ][nbase + g]);
                bf[nf][1] = __float_as_uint(Bs[ks + tig + 4][nbase + g]);
            }
#pragma unroll
            for (int mf = 0; mf < 2; mf++)
#pragma unroll
                for (int nf = 0; nf < 4; nf++) {
                    asm volatile(
                        "mma.sync.aligned.m16n8k8.row.col.f32.tf32.tf32.f32 "
                        "{%0,%1,%2,%3}, {%4,%5,%6,%7}, {%8,%9}, {%0,%1,%2,%3};"
                        : "+f"(c[mf][nf][0]), "+f"(c[mf][nf][1]),
                          "+f"(c[mf][nf][2]), "+f"(c[mf][nf][3])
                        : "r"(af[mf][0]), "r"(af[mf][1]),
                          "r"(af[mf][2]), "r"(af[mf][3]),
                          "r"(bf[nf][0]), "r"(bf[nf][1]));
                }
        }
        __syncthreads();
    }

    // epilogue: store feat1 + attention dots for this head
    float alv[4][2], arv[4][2];
#pragma unroll
    for (int nf = 0; nf < 4; nf++)
#pragma unroll
        for (int j = 0; j < 2; j++) {
            int col = warpN * 32 + nf * 8 + 2 * tig + j;
            alv[nf][j] = al[h * D1 + col];
            arv[nf][j] = ar[h * D1 + col];
        }

#pragma unroll
    for (int mf = 0; mf < 2; mf++) {
        int lr0 = warpM * 32 + mf * 16 + g;       // local row (c0,c1)
        int lr1 = lr0 + 8;                        // local row (c2,c3)
        int r0g = row0 + lr0, r1g = row0 + lr1;
        float el0 = 0.f, er0 = 0.f, el1v = 0.f, er1v = 0.f;
#pragma unroll
        for (int nf = 0; nf < 4; nf++) {
            int colw = warpN * 32 + nf * 8 + 2 * tig;
            if (r0g < N)
                *(float2*)&g_feat1[r0g * HD + col0 + colw] =
                    make_float2(c[mf][nf][0], c[mf][nf][1]);
            if (r1g < N)
                *(float2*)&g_feat1[r1g * HD + col0 + colw] =
                    make_float2(c[mf][nf][2], c[mf][nf][3]);
            el0 += c[mf][nf][0] * alv[nf][0] + c[mf][nf][1] * alv[nf][1];
            er0 += c[mf][nf][0] * arv[nf][0] + c[mf][nf][1] * arv[nf][1];
            el1v += c[mf][nf][2] * alv[nf][0] + c[mf][nf][3] * alv[nf][1];
            er1v += c[mf][nf][2] * arv[nf][0] + c[mf][nf][3] * arv[nf][1];
        }
        // reduce across the 4 lanes of each thread-group (tig dimension)
#pragma unroll
        for (int o = 1; o < 4; o <<= 1) {
            el0  += __shfl_xor_sync(0xffffffffu, el0,  o, 4);
            er0  += __shfl_xor_sync(0xffffffffu, er0,  o, 4);
            el1v += __shfl_xor_sync(0xffffffffu, el1v, o, 4);
            er1v += __shfl_xor_sync(0xffffffffu, er1v, o, 4);
        }
        if (tig == 0) {
            atomicAdd(&el_sh[lr0], el0);  atomicAdd(&er_sh[lr0], er0);
            atomicAdd(&el_sh[lr1], el1v); atomicAdd(&er_sh[lr1], er1v);
        }
    }
    __syncthreads();
    if (tid < 128) {
        int r = row0 + tid;
        if (r < N) {
            g_el1[r * NH + h] = el_sh[tid];
            g_er1[r * NH + h] = er_sh[tid];
        }
    }
}

// ---------------- layer1: softmax + aggregation + elu (fused, smem weights) -
__global__ void sfm_agg1_kernel() {
    int n = blockIdx.x;
    int tid = threadIdx.x;
    int wid = tid >> 5, lane = tid & 31;
    __shared__ float mx_sh[NH], invden_sh[NH];
    __shared__ float w_sh[NH][128];
    __shared__ int   s_sh[128];
    int r0 = g_rowptr[n];
    int deg = g_rowptr[n + 1] - r0;

    if (wid < NH) {
        int h = wid;
        float ern = g_er1[n * NH + h];
        float mx = -INFINITY;
        for (int i = lane; i < deg; i += 32) {
            int s = g_esrc[r0 + i];
            float x = g_el1[s * NH + h] + ern;
            x = (x > 0.f) ? x : NEG * x;
            mx = fmaxf(mx, x);
        }
#pragma unroll
        for (int o = 16; o; o >>= 1)
            mx = fmaxf(mx, __shfl_xor_sync(0xffffffffu, mx, o));
        float den = 0.f;
        for (int i = lane; i < deg; i += 32) {
            int s = g_esrc[r0 + i];
            float x = g_el1[s * NH + h] + ern;
            x = (x > 0.f) ? x : NEG * x;
            den += expf(x - mx);
        }
#pragma unroll
        for (int o = 16; o; o >>= 1)
            den += __shfl_xor_sync(0xffffffffu, den, o);
        if (lane == 0) {
            mx_sh[h] = mx;
            invden_sh[h] = 1.f / fmaxf(den, 1e-9f);
        }
    }
    __syncthreads();

    int c = tid;
    int hc = c >> 6;
    float acc = 0.f;
    for (int i0 = 0; i0 < deg; i0 += 128) {
        int cnt = min(128, deg - i0);
        if (tid < cnt) s_sh[tid] = g_esrc[r0 + i0 + tid];
        if (wid < NH) {
            int h = wid;
            float ern = g_er1[n * NH + h];
            float mxh = mx_sh[h], idh = invden_sh[h];
            for (int j = lane; j < cnt; j += 32) {
                int s = g_esrc[r0 + i0 + j];
                float x = g_el1[s * NH + h] + ern;
                x = (x > 0.f) ? x : NEG * x;
                w_sh[h][j] = expf(x - mxh) * idh;
            }
        }
        __syncthreads();
        for (int j = 0; j < cnt; j++)
            acc += w_sh[hc][j] * g_feat1[s_sh[j] * HD + c];
        __syncthreads();
    }
    g_h2[n * HD + c] = (acc > 0.f) ? acc : expm1f(acc);   // elu fused
}

// ---------------- layer2 GEMM + attention dots (block per node) --------------
__global__ void layer2_node_kernel(const float* __restrict__ W2,
                                   const float* __restrict__ al2,
                                   const float* __restrict__ ar2) {
    int n = blockIdx.x;
    int t = threadIdx.x;          // 256
    __shared__ float sh[HD];
    __shared__ float red[4][OUTF];
    __shared__ float sl[OUTF], sr[OUTF];

    sh[t] = g_h2[n * HD + t];
    __syncthreads();

    if (t < 4 * OUTF) {
        int col = t % OUTF, part = t / OUTF;
        float acc = 0.f;
        int k0 = part * 64;
#pragma unroll 8
        for (int k = 0; k < 64; k++)
            acc += sh[k0 + k] * W2[(k0 + k) * OUTF + col];
        red[part][col] = acc;
    }
    __syncthreads();

    if (t < OUTF) {
        float f = red[0][t] + red[1][t] + red[2][t] + red[3][t];
        g_feat2[n * OUTF + t] = f;
        sl[t] = f * al2[t];
        sr[t] = f * ar2[t];
    }
    __syncthreads();

    if (t < 32) {
        float a = sl[t] + (t + 32 < OUTF ? sl[t + 32] : 0.f);
        float b = sr[t] + (t + 32 < OUTF ? sr[t + 32] : 0.f);
#pragma unroll
        for (int o = 16; o; o >>= 1) {
            a += __shfl_xor_sync(0xffffffffu, a, o);
            b += __shfl_xor_sync(0xffffffffu, b, o);
        }
        if (t == 0) { g_el2[n] = a; g_er2[n] = b; }
    }
}

// ---------------- layer2: softmax + aggregation + log_softmax (fused) -------
__global__ void agg2_ls_kernel(float* __restrict__ out, int N) {
    int warp = threadIdx.x >> 5;
    int lane = threadIdx.x & 31;
    int n = blockIdx.x * 4 + warp;
    if (n >= N) return;
    int r0 = g_rowptr[n];
    int deg = g_rowptr[n + 1] - r0;
    float ern = g_er2[n];

    float mx = -INFINITY;
    for (int i = lane; i < deg; i += 32) {
        int s = g_esrc[r0 + i];
        float x = g_el2[s] + ern;
        x = (x > 0.f) ? x : NEG * x;
        mx = fmaxf(mx, x);
    }
#pragma unroll
    for (int o = 16; o; o >>= 1)
        mx = fmaxf(mx, __shfl_xor_sync(0xffffffffu, mx, o));

    float den = 0.f;
    for (int i = lane; i < deg; i += 32) {
        int s = g_esrc[r0 + i];
        float x = g_el2[s] + ern;
        x = (x > 0.f) ? x : NEG * x;
        den += expf(x - mx);
    }
#pragma unroll
    for (int o = 16; o; o >>= 1)
        den += __shfl_xor_sync(0xffffffffu, den, o);
    den = fmaxf(den, 1e-9f);

    bool hi = (lane + 32) < OUTF;
    float a0 = 0.f, a1 = 0.f;
    for (int i = 0; i < deg; i++) {
        int s = g_esrc[r0 + i];
        float x = g_el2[s] + ern;
        x = (x > 0.f) ? x : NEG * x;
        float w = expf(x - mx);
        a0 += w * g_feat2[s * OUTF + lane];
        if (hi) a1 += w * g_feat2[s * OUTF + lane + 32];
    }
    a0 /= den;
    a1 /= den;

    float v0 = a0;
    float v1 = hi ? a1 : -INFINITY;
    float m2 = fmaxf(v0, v1);
#pragma unroll
    for (int o = 16; o; o >>= 1)
        m2 = fmaxf(m2, __shfl_xor_sync(0xffffffffu, m2, o));
    float s_ = expf(v0 - m2) + (hi ? expf(v1 - m2) : 0.f);
#pragma unroll
    for (int o = 16; o; o >>= 1)
        s_ += __shfl_xor_sync(0xffffffffu, s_, o);
    float ls = logf(s_) + m2;
    out[n * OUTF + lane] = v0 - ls;
    if (hi) out[n * OUTF + lane + 32] = v1 - ls;
}

// ---------------- launch ----------------
extern "C" void kernel_launch(void* const* d_in, const int* in_sizes, int n_in,
                              void* d_out, int out_size) {
    const float* features = (const float*)d_in[0];
    const int*   src      = (const int*)d_in[1];
    const int*   dst      = (const int*)d_in[2];
    const float* W1       = (const float*)d_in[3];
    const float* al1      = (const float*)d_in[4];
    const float* ar1      = (const float*)d_in[5];
    const float* W2       = (const float*)d_in[6];
    const float* al2      = (const float*)d_in[7];
    const float* ar2      = (const float*)d_in[8];
    float* out = (float*)d_out;

    int N = in_sizes[0] / IN_F;   // 10000
    int E = in_sizes[1];          // 320000
    if (N > N_NODES) N = N_NODES;
    if (E > N_EDGES) E = N_EDGES;

    // CSR build (group by dst)
    init_kernel<<<20, 1024>>>();
    count_kernel<<<(E + 255) / 256, 256>>>(dst, E);
    scan_kernel<<<1, 1024>>>();
    scatter_kernel<<<(E + 255) / 256, 256>>>(src, dst, E);

    // layer 1
    dim3 g1((N + 127) / 128, NH);
    gemm1_attn_kernel<<<g1, 256>>>(features, W1, al1, ar1, N);
    sfm_agg1_kernel<<<N, 256>>>();

    // layer 2
    layer2_node_kernel<<<N, 256>>>(W2, al2, ar2);
    agg2_ls_kernel<<<(N + 3) / 4, 128>>>(out, N);
}

// round 10
// speedup vs baseline: 1.8646x; 1.2943x over previous
#include <cuda_runtime.h>
#include <cuda_fp16.h>
#include <math.h>
#include <stdint.h>

#define N_NODES 10000
#define N_EDGES 320000
#define IN_F    256
#define HD      256
#define NH      4
#define D1      64
#define OUTF    47
#define OUTP    48
#define NEG     0.2f

// ---------------- scratch: vector-typed so 16B alignment is guaranteed ------
__device__ uint4  g_feat1v[N_NODES * 32];   // 256 fp16 ch = 32 uint4 per node
__device__ float4 g_h2v   [N_NODES * 64];   // 256 fp32  = 64 float4 per node
__device__ float4 g_el1v  [N_NODES];        // 4 heads
__device__ float4 g_er1v  [N_NODES];
__device__ float  g_feat2 [N_NODES * OUTP];
__device__ float  g_el2   [N_NODES];
__device__ float  g_er2   [N_NODES];

__device__ int   g_deg   [N_NODES];
__device__ int   g_rowptr[N_NODES + 1];
__device__ int   g_cursor[N_NODES];
__device__ int   g_esrc  [N_EDGES];

__device__ __forceinline__ float tf32r(float x) {
    uint32_t u;
    asm("cvt.rna.tf32.f32 %0, %1;" : "=r"(u) : "f"(x));
    return __uint_as_float(u);
}

// ---------------- init ----------------
__global__ void init_kernel() {
    int i = blockIdx.x * blockDim.x + threadIdx.x;
    int stride = gridDim.x * blockDim.x;
    for (int j = i; j < N_NODES; j += stride) { g_deg[j] = 0; g_cursor[j] = 0; }
}

// ---------------- CSR build (vectorized; d_in ptrs are cudaMalloc-aligned) --
__global__ void count_kernel(const int* __restrict__ dst, int E) {
    int e4 = (blockIdx.x * blockDim.x + threadIdx.x) * 4;
    if (e4 + 3 < E) {
        int4 d = *(const int4*)&dst[e4];
        atomicAdd(&g_deg[d.x], 1); atomicAdd(&g_deg[d.y], 1);
        atomicAdd(&g_deg[d.z], 1); atomicAdd(&g_deg[d.w], 1);
    } else {
        for (int e = e4; e < E; e++) atomicAdd(&g_deg[dst[e]], 1);
    }
}

__global__ void scan_kernel() {
    __shared__ int part[1024];
    const int PER = (N_NODES + 1023) / 1024;   // 10
    int t = threadIdx.x;
    int base = t * PER;
    int loc[PER];
    int sum = 0;
#pragma unroll
    for (int i = 0; i < PER; i++) {
        int idx = base + i;
        int v = (idx < N_NODES) ? g_deg[idx] : 0;
        sum += v;
        loc[i] = sum;
    }
    part[t] = sum;
    __syncthreads();
    for (int off = 1; off < 1024; off <<= 1) {
        int add = (t >= off) ? part[t - off] : 0;
        __syncthreads();
        part[t] += add;
        __syncthreads();
    }
    int offset = (t > 0) ? part[t - 1] : 0;
#pragma unroll
    for (int i = 0; i < PER; i++) {
        int idx = base + i;
        if (idx < N_NODES) g_rowptr[idx + 1] = offset + loc[i];
    }
    if (t == 0) g_rowptr[0] = 0;
}

__global__ void scatter_kernel(const int* __restrict__ src,
                               const int* __restrict__ dst, int E) {
    int e4 = (blockIdx.x * blockDim.x + threadIdx.x) * 4;
    if (e4 + 3 < E) {
        int4 s = *(const int4*)&src[e4];
        int4 d = *(const int4*)&dst[e4];
        g_esrc[g_rowptr[d.x] + atomicAdd(&g_cursor[d.x], 1)] = s.x;
        g_esrc[g_rowptr[d.y] + atomicAdd(&g_cursor[d.y], 1)] = s.y;
        g_esrc[g_rowptr[d.z] + atomicAdd(&g_cursor[d.z], 1)] = s.z;
        g_esrc[g_rowptr[d.w] + atomicAdd(&g_cursor[d.w], 1)] = s.w;
    } else {
        for (int e = e4; e < E; e++) {
            int d = dst[e];
            g_esrc[g_rowptr[d] + atomicAdd(&g_cursor[d], 1)] = src[e];
        }
    }
}

// ---------------- GEMM1 (tf32 mma) + attention dots; fp16 feature store -----
__global__ void gemm1_attn_kernel(const float* __restrict__ A,
                                  const float* __restrict__ B,
                                  const float* __restrict__ al,
                                  const float* __restrict__ ar, int N) {
    __shared__ float As[128][36];
    __shared__ float Bs[32][72];
    __shared__ float el_sh[128], er_sh[128];

    int tid  = threadIdx.x;
    int wid  = tid >> 5, lane = tid & 31;
    int g    = lane >> 2, tig = lane & 3;
    int warpM = wid >> 1, warpN = wid & 1;
    int h    = blockIdx.y;
    int row0 = blockIdx.x * 128, col0 = h * 64;

    __half2* f1h = reinterpret_cast<__half2*>(g_feat1v);
    float*   el1 = reinterpret_cast<float*>(g_el1v);
    float*   er1 = reinterpret_cast<float*>(g_er1v);

    if (tid < 128) { el_sh[tid] = 0.f; er_sh[tid] = 0.f; }

    float c[2][4][4];
#pragma unroll
    for (int mf = 0; mf < 2; mf++)
#pragma unroll
        for (int nf = 0; nf < 4; nf++)
#pragma unroll
            for (int j = 0; j < 4; j++) c[mf][nf][j] = 0.f;

    for (int kk = 0; kk < IN_F; kk += 32) {
#pragma unroll
        for (int i = 0; i < 4; i++) {
            int idx = tid + i * 256;
            int m = idx >> 3, kq = (idx & 7) * 4;
            int r = row0 + m;
            float4 v = (r < N) ? *(const float4*)&A[r * IN_F + kk + kq]
                               : make_float4(0.f, 0.f, 0.f, 0.f);
            As[m][kq + 0] = tf32r(v.x); As[m][kq + 1] = tf32r(v.y);
            As[m][kq + 2] = tf32r(v.z); As[m][kq + 3] = tf32r(v.w);
        }
#pragma unroll
        for (int i = 0; i < 2; i++) {
            int idx = tid + i * 256;
            int k = idx >> 4, nq = (idx & 15) * 4;
            float4 v = *(const float4*)&B[(kk + k) * HD + col0 + nq];
            Bs[k][nq + 0] = tf32r(v.x); Bs[k][nq + 1] = tf32r(v.y);
            Bs[k][nq + 2] = tf32r(v.z); Bs[k][nq + 3] = tf32r(v.w);
        }
        __syncthreads();

#pragma unroll
        for (int ks = 0; ks < 32; ks += 8) {
            uint32_t af[2][4], bf[4][2];
#pragma unroll
            for (int mf = 0; mf < 2; mf++) {
                int mbase = warpM * 32 + mf * 16;
                af[mf][0] = __float_as_uint(As[mbase + g    ][ks + tig    ]);
                af[mf][1] = __float_as_uint(As[mbase + g + 8][ks + tig    ]);
                af[mf][2] = __float_as_uint(As[mbase + g    ][ks + tig + 4]);
                af[mf][3] = __float_as_uint(As[mbase + g + 8][ks + tig + 4]);
            }
#pragma unroll
            for (int nf = 0; nf < 4; nf++) {
                int nbase = warpN * 32 + nf * 8;
                bf[nf][0] = __float_as_uint(Bs[ks + tig    ][nbase + g]);
                bf[nf][1] = __float_as_uint(Bs[ks + tig + 4][nbase + g]);
            }
#pragma unroll
            for (int mf = 0; mf < 2; mf++)
#pragma unroll
                for (int nf = 0; nf < 4; nf++) {
                    asm volatile(
                        "mma.sync.aligned.m16n8k8.row.col.f32.tf32.tf32.f32 "
                        "{%0,%1,%2,%3}, {%4,%5,%6,%7}, {%8,%9}, {%0,%1,%2,%3};"
                        : "+f"(c[mf][nf][0]), "+f"(c[mf][nf][1]),
                          "+f"(c[mf][nf][2]), "+f"(c[mf][nf][3])
                        : "r"(af[mf][0]), "r"(af[mf][1]),
                          "r"(af[mf][2]), "r"(af[mf][3]),
                          "r"(bf[nf][0]), "r"(bf[nf][1]));
                }
        }
        __syncthreads();
    }

    float alv[4][2], arv[4][2];
#pragma unroll
    for (int nf = 0; nf < 4; nf++)
#pragma unroll
        for (int j = 0; j < 2; j++) {
            int col = warpN * 32 + nf * 8 + 2 * tig + j;
            alv[nf][j] = al[h * D1 + col];
            arv[nf][j] = ar[h * D1 + col];
        }

#pragma unroll
    for (int mf = 0; mf < 2; mf++) {
        int lr0 = warpM * 32 + mf * 16 + g;
        int lr1 = lr0 + 8;
        int r0g = row0 + lr0, r1g = row0 + lr1;
        float el0 = 0.f, er0 = 0.f, el1v = 0.f, er1v = 0.f;
#pragma unroll
        for (int nf = 0; nf < 4; nf++) {
            int colw = warpN * 32 + nf * 8 + 2 * tig;
            int cp = (col0 + colw) >> 1;
            if (r0g < N)
                f1h[r0g * (HD/2) + cp] = __floats2half2_rn(c[mf][nf][0], c[mf][nf][1]);
            if (r1g < N)
                f1h[r1g * (HD/2) + cp] = __floats2half2_rn(c[mf][nf][2], c[mf][nf][3]);
            el0 += c[mf][nf][0] * alv[nf][0] + c[mf][nf][1] * alv[nf][1];
            er0 += c[mf][nf][0] * arv[nf][0] + c[mf][nf][1] * arv[nf][1];
            el1v += c[mf][nf][2] * alv[nf][0] + c[mf][nf][3] * alv[nf][1];
            er1v += c[mf][nf][2] * arv[nf][0] + c[mf][nf][3] * arv[nf][1];
        }
#pragma unroll
        for (int o = 1; o < 4; o <<= 1) {
            el0  += __shfl_xor_sync(0xffffffffu, el0,  o, 4);
            er0  += __shfl_xor_sync(0xffffffffu, er0,  o, 4);
            el1v += __shfl_xor_sync(0xffffffffu, el1v, o, 4);
            er1v += __shfl_xor_sync(0xffffffffu, er1v, o, 4);
        }
        if (tig == 0) {
            atomicAdd(&el_sh[lr0], el0);  atomicAdd(&er_sh[lr0], er0);
            atomicAdd(&el_sh[lr1], el1v); atomicAdd(&er_sh[lr1], er1v);
        }
    }
    __syncthreads();
    if (tid < 128) {
        int r = row0 + tid;
        if (r < N) {
            el1[r * NH + h] = el_sh[tid];
            er1[r * NH + h] = er_sh[tid];
        }
    }
}

// ---------------- layer1: softmax + agg + elu; 8 nodes/block ----------------
// CH=32: one warp (32 lanes) fully populates each staging chunk.
#define CH 32
__global__ void sfm_agg1_kernel(int N) {
    __shared__ float mx_sh[8][NH], invden_sh[8][NH];
    __shared__ int   s_sh[8][CH];
    __shared__ float w_sh[8][NH][CH];
    __shared__ int   deg_sh[8], cnt_sh[8];

    int tid = threadIdx.x;
    int wid = tid >> 5, lane = tid & 31;
    int n = blockIdx.x * 8 + wid;
    bool valid = n < N;
    int r0 = 0, deg = 0;
    if (valid) { r0 = g_rowptr[n]; deg = g_rowptr[n + 1] - r0; }
    if (lane == 0) deg_sh[wid] = deg;

    float4 ern4 = valid ? g_er1v[n] : make_float4(0.f, 0.f, 0.f, 0.f);
    float mx[NH] = {-INFINITY, -INFINITY, -INFINITY, -INFINITY};
    for (int i = lane; i < deg; i += 32) {
        int s = g_esrc[r0 + i];
        float4 el4 = g_el1v[s];
        float x0 = el4.x + ern4.x; x0 = (x0 > 0.f) ? x0 : NEG * x0;
        float x1 = el4.y + ern4.y; x1 = (x1 > 0.f) ? x1 : NEG * x1;
        float x2 = el4.z + ern4.z; x2 = (x2 > 0.f) ? x2 : NEG * x2;
        float x3 = el4.w + ern4.w; x3 = (x3 > 0.f) ? x3 : NEG * x3;
        mx[0] = fmaxf(mx[0], x0); mx[1] = fmaxf(mx[1], x1);
        mx[2] = fmaxf(mx[2], x2); mx[3] = fmaxf(mx[3], x3);
    }
#pragma unroll
    for (int h = 0; h < NH; h++)
#pragma unroll
        for (int o = 16; o; o >>= 1)
            mx[h] = fmaxf(mx[h], __shfl_xor_sync(0xffffffffu, mx[h], o));

    float den[NH] = {0.f, 0.f, 0.f, 0.f};
    for (int i = lane; i < deg; i += 32) {
        int s = g_esrc[r0 + i];
        float4 el4 = g_el1v[s];
        float x0 = el4.x + ern4.x; x0 = (x0 > 0.f) ? x0 : NEG * x0;
        float x1 = el4.y + ern4.y; x1 = (x1 > 0.f) ? x1 : NEG * x1;
        float x2 = el4.z + ern4.z; x2 = (x2 > 0.f) ? x2 : NEG * x2;
        float x3 = el4.w + ern4.w; x3 = (x3 > 0.f) ? x3 : NEG * x3;
        den[0] += __expf(x0 - mx[0]); den[1] += __expf(x1 - mx[1]);
        den[2] += __expf(x2 - mx[2]); den[3] += __expf(x3 - mx[3]);
    }
#pragma unroll
    for (int h = 0; h < NH; h++)
#pragma unroll
        for (int o = 16; o; o >>= 1)
            den[h] += __shfl_xor_sync(0xffffffffu, den[h], o);
    if (lane == 0) {
#pragma unroll
        for (int h = 0; h < NH; h++) {
            mx_sh[wid][h] = mx[h];
            invden_sh[wid][h] = 1.f / fmaxf(den[h], 1e-9f);
        }
    }
    __syncthreads();

    int degmax = 0;
#pragma unroll
    for (int j = 0; j < 8; j++) degmax = max(degmax, deg_sh[j]);

    int hme = lane >> 3;
    float acc[8] = {};
    float mxw[NH], idw[NH];
#pragma unroll
    for (int h = 0; h < NH; h++) { mxw[h] = mx_sh[wid][h]; idw[h] = invden_sh[wid][h]; }

    for (int i0 = 0; i0 < degmax; i0 += CH) {
        int cnt = min(CH, deg - i0); if (cnt < 0) cnt = 0;
        if (lane == 0) cnt_sh[wid] = cnt;
        if (lane < cnt) {
            int s = g_esrc[r0 + i0 + lane];
            s_sh[wid][lane] = s;
            float4 el4 = g_el1v[s];
            float x0 = el4.x + ern4.x; x0 = (x0 > 0.f) ? x0 : NEG * x0;
            float x1 = el4.y + ern4.y; x1 = (x1 > 0.f) ? x1 : NEG * x1;
            float x2 = el4.z + ern4.z; x2 = (x2 > 0.f) ? x2 : NEG * x2;
            float x3 = el4.w + ern4.w; x3 = (x3 > 0.f) ? x3 : NEG * x3;
            w_sh[wid][0][lane] = __expf(x0 - mxw[0]) * idw[0];
            w_sh[wid][1][lane] = __expf(x1 - mxw[1]) * idw[1];
            w_sh[wid][2][lane] = __expf(x2 - mxw[2]) * idw[2];
            w_sh[wid][3][lane] = __expf(x3 - mxw[3]) * idw[3];
        }
        __syncthreads();
        int cj = cnt_sh[wid];
        for (int i = 0; i < cj; i++) {
            int s = s_sh[wid][i];
            float w = w_sh[wid][hme][i];
            uint4 raw = g_feat1v[s * 32 + lane];       // 8 fp16 channels
            float2 p0 = __half22float2(*reinterpret_cast<__half2*>(&raw.x));
            float2 p1 = __half22float2(*reinterpret_cast<__half2*>(&raw.y));
            float2 p2 = __half22float2(*reinterpret_cast<__half2*>(&raw.z));
            float2 p3 = __half22float2(*reinterpret_cast<__half2*>(&raw.w));
            acc[0] += w * p0.x; acc[1] += w * p0.y;
            acc[2] += w * p1.x; acc[3] += w * p1.y;
            acc[4] += w * p2.x; acc[5] += w * p2.y;
            acc[6] += w * p3.x; acc[7] += w * p3.y;
        }
        __syncthreads();
    }

    if (valid) {
        float o[8];
#pragma unroll
        for (int q = 0; q < 8; q++)
            o[q] = (acc[q] > 0.f) ? acc[q] : expm1f(acc[q]);
        g_h2v[n * 64 + lane * 2]     = make_float4(o[0], o[1], o[2], o[3]);
        g_h2v[n * 64 + lane * 2 + 1] = make_float4(o[4], o[5], o[6], o[7]);
    }
}

// ---------------- layer2 GEMM (tf32 mma) + attention dots -------------------
__global__ void gemm2_attn_kernel(const float* __restrict__ W2,
                                  const float* __restrict__ al2,
                                  const float* __restrict__ ar2, int N) {
    __shared__ float As[128][36];
    __shared__ float Bs[32][72];
    __shared__ float el_sh[128], er_sh[128];

    int tid  = threadIdx.x;
    int wid  = tid >> 5, lane = tid & 31;
    int g    = lane >> 2, tig = lane & 3;
    int warpM = wid >> 1, warpN = wid & 1;
    int row0 = blockIdx.x * 128;

    if (tid < 128) { el_sh[tid] = 0.f; er_sh[tid] = 0.f; }

    float c[2][4][4];
#pragma unroll
    for (int mf = 0; mf < 2; mf++)
#pragma unroll
        for (int nf = 0; nf < 4; nf++)
#pragma unroll
            for (int j = 0; j < 4; j++) c[mf][nf][j] = 0.f;

    for (int kk = 0; kk < HD; kk += 32) {
#pragma unroll
        for (int i = 0; i < 4; i++) {
            int idx = tid + i * 256;
            int m = idx >> 3, kq = (idx & 7) * 4;
            int r = row0 + m;
            float4 v = (r < N) ? g_h2v[r * 64 + (kk + kq) / 4]
                               : make_float4(0.f, 0.f, 0.f, 0.f);
            As[m][kq + 0] = tf32r(v.x); As[m][kq + 1] = tf32r(v.y);
            As[m][kq + 2] = tf32r(v.z); As[m][kq + 3] = tf32r(v.w);
        }
#pragma unroll
        for (int i = 0; i < 8; i++) {
            int idx = tid + i * 256;
            int k = idx >> 6, nn = idx & 63;
            Bs[k][nn] = (nn < OUTF) ? tf32r(W2[(kk + k) * OUTF + nn]) : 0.f;
        }
        __syncthreads();

#pragma unroll
        for (int ks = 0; ks < 32; ks += 8) {
            uint32_t af[2][4], bf[4][2];
#pragma unroll
            for (int mf = 0; mf < 2; mf++) {
                int mbase = warpM * 32 + mf * 16;
                af[mf][0] = __float_as_uint(As[mbase + g    ][ks + tig    ]);
                af[mf][1] = __float_as_uint(As[mbase + g + 8][ks + tig    ]);
                af[mf][2] = __float_as_uint(As[mbase + g    ][ks + tig + 4]);
                af[mf][3] = __float_as_uint(As[mbase + g + 8][ks + tig + 4]);
            }
#pragma unroll
            for (int nf = 0; nf < 4; nf++) {
                int nbase = warpN * 32 + nf * 8;
                bf[nf][0] = __float_as_uint(Bs[ks + tig    ][nbase + g]);
                bf[nf][1] = __float_as_uint(Bs[ks + tig + 4][nbase + g]);
            }
#pragma unroll
            for (int mf = 0; mf < 2; mf++)
#pragma unroll
                for (int nf = 0; nf < 4; nf++) {
                    asm volatile(
                        "mma.sync.aligned.m16n8k8.row.col.f32.tf32.tf32.f32 "
                        "{%0,%1,%2,%3}, {%4,%5,%6,%7}, {%8,%9}, {%0,%1,%2,%3};"
                        : "+f"(c[mf][nf][0]), "+f"(c[mf][nf][1]),
                          "+f"(c[mf][nf][2]), "+f"(c[mf][nf][3])
                        : "r"(af[mf][0]), "r"(af[mf][1]),
                          "r"(af[mf][2]), "r"(af[mf][3]),
                          "r"(bf[nf][0]), "r"(bf[nf][1]));
                }
        }
        __syncthreads();
    }

    float alv[4][2], arv[4][2];
#pragma unroll
    for (int nf = 0; nf < 4; nf++)
#pragma unroll
        for (int j = 0; j < 2; j++) {
            int col = warpN * 32 + nf * 8 + 2 * tig + j;
            alv[nf][j] = (col < OUTF) ? al2[col] : 0.f;
            arv[nf][j] = (col < OUTF) ? ar2[col] : 0.f;
        }

#pragma unroll
    for (int mf = 0; mf < 2; mf++) {
        int lr0 = warpM * 32 + mf * 16 + g;
        int lr1 = lr0 + 8;
        int r0g = row0 + lr0, r1g = row0 + lr1;
        float el0 = 0.f, er0 = 0.f, el1v = 0.f, er1v = 0.f;
#pragma unroll
        for (int nf = 0; nf < 4; nf++) {
            int colw = warpN * 32 + nf * 8 + 2 * tig;
#pragma unroll
            for (int j = 0; j < 2; j++) {
                int col = colw + j;
                if (col < OUTF) {
                    if (r0g < N) g_feat2[r0g * OUTP + col] = c[mf][nf][j];
                    if (r1g < N) g_feat2[r1g * OUTP + col] = c[mf][nf][2 + j];
                }
            }
            el0 += c[mf][nf][0] * alv[nf][0] + c[mf][nf][1] * alv[nf][1];
            er0 += c[mf][nf][0] * arv[nf][0] + c[mf][nf][1] * arv[nf][1];
            el1v += c[mf][nf][2] * alv[nf][0] + c[mf][nf][3] * alv[nf][1];
            er1v += c[mf][nf][2] * arv[nf][0] + c[mf][nf][3] * arv[nf][1];
        }
#pragma unroll
        for (int o = 1; o < 4; o <<= 1) {
            el0  += __shfl_xor_sync(0xffffffffu, el0,  o, 4);
            er0  += __shfl_xor_sync(0xffffffffu, er0,  o, 4);
            el1v += __shfl_xor_sync(0xffffffffu, el1v, o, 4);
            er1v += __shfl_xor_sync(0xffffffffu, er1v, o, 4);
        }
        if (tig == 0) {
            atomicAdd(&el_sh[lr0], el0);  atomicAdd(&er_sh[lr0], er0);
            atomicAdd(&el_sh[lr1], el1v); atomicAdd(&er_sh[lr1], er1v);
        }
    }
    __syncthreads();
    if (tid < 128) {
        int r = row0 + tid;
        if (r < N) {
            g_el2[r] = el_sh[tid];
            g_er2[r] = er_sh[tid];
        }
    }
}

// ---------------- layer2: softmax + agg + log_softmax (warp per node) -------
__global__ void agg2_ls_kernel(float* __restrict__ out, int N) {
    int warp = threadIdx.x >> 5;
    int lane = threadIdx.x & 31;
    int n = blockIdx.x * 4 + warp;
    if (n >= N) return;
    int r0 = g_rowptr[n];
    int deg = g_rowptr[n + 1] - r0;
    float ern = g_er2[n];

    float mx = -INFINITY;
    for (int i = lane; i < deg; i += 32) {
        int s = g_esrc[r0 + i];
        float x = g_el2[s] + ern;
        x = (x > 0.f) ? x : NEG * x;
        mx = fmaxf(mx, x);
    }
#pragma unroll
    for (int o = 16; o; o >>= 1)
        mx = fmaxf(mx, __shfl_xor_sync(0xffffffffu, mx, o));

    float den = 0.f;
    for (int i = lane; i < deg; i += 32) {
        int s = g_esrc[r0 + i];
        float x = g_el2[s] + ern;
        x = (x > 0.f) ? x : NEG * x;
        den += __expf(x - mx);
    }
#pragma unroll
    for (int o = 16; o; o >>= 1)
        den += __shfl_xor_sync(0xffffffffu, den, o);
    den = fmaxf(den, 1e-9f);

    bool hi = (lane + 32) < OUTF;
    float a0 = 0.f, a1 = 0.f;
    for (int i = 0; i < deg; i++) {
        int s = g_esrc[r0 + i];
        float x = g_el2[s] + ern;
        x = (x > 0.f) ? x : NEG * x;
        float w = __expf(x - mx);
        a0 += w * g_feat2[s * OUTP + lane];
        if (hi) a1 += w * g_feat2[s * OUTP + lane + 32];
    }
    a0 /= den;
    a1 /= den;

    float v0 = a0;
    float v1 = hi ? a1 : -INFINITY;
    float m2 = fmaxf(v0, v1);
#pragma unroll
    for (int o = 16; o; o >>= 1)
        m2 = fmaxf(m2, __shfl_xor_sync(0xffffffffu, m2, o));
    float s_ = expf(v0 - m2) + (hi ? expf(v1 - m2) : 0.f);
#pragma unroll
    for (int o = 16; o; o >>= 1)
        s_ += __shfl_xor_sync(0xffffffffu, s_, o);
    float ls = logf(s_) + m2;
    out[n * OUTF + lane] = v0 - ls;
    if (hi) out[n * OUTF + lane + 32] = v1 - ls;
}

// ---------------- launch ----------------
extern "C" void kernel_launch(void* const* d_in, const int* in_sizes, int n_in,
                              void* d_out, int out_size) {
    const float* features = (const float*)d_in[0];
    const int*   src      = (const int*)d_in[1];
    const int*   dst      = (const int*)d_in[2];
    const float* W1       = (const float*)d_in[3];
    const float* al1      = (const float*)d_in[4];
    const float* ar1      = (const float*)d_in[5];
    const float* W2       = (const float*)d_in[6];
    const float* al2      = (const float*)d_in[7];
    const float* ar2      = (const float*)d_in[8];
    float* out = (float*)d_out;

    int N = in_sizes[0] / IN_F;   // 10000
    int E = in_sizes[1];          // 320000
    if (N > N_NODES) N = N_NODES;
    if (E > N_EDGES) E = N_EDGES;

    init_kernel<<<20, 1024>>>();
    int e4blocks = (E / 4 + 255) / 256 + 1;
    count_kernel<<<e4blocks, 256>>>(dst, E);
    scan_kernel<<<1, 1024>>>();
    scatter_kernel<<<e4blocks, 256>>>(src, dst, E);

    dim3 g1((N + 127) / 128, NH);
    gemm1_attn_kernel<<<g1, 256>>>(features, W1, al1, ar1, N);
    sfm_agg1_kernel<<<(N + 7) / 8, 256>>>(N);

    gemm2_attn_kernel<<<(N + 127) / 128, 256>>>(W2, al2, ar2, N);
    agg2_ls_kernel<<<(N + 3) / 4, 128>>>(out, N);
}

// round 11
// speedup vs baseline: 2.0587x; 1.1041x over previous
#include <cuda_runtime.h>
#include <cuda_fp16.h>
#include <math.h>
#include <stdint.h>

#define N_NODES 10000
#define N_EDGES 320000
#define IN_F    256
#define HD      256
#define NH      4
#define D1      64
#define OUTF    47
#define OUTP    48
#define NEG     0.2f

// ---------------- scratch: vector-typed so 16B alignment is guaranteed ------
__device__ uint4  g_feat1v[N_NODES * 32];   // 256 fp16 ch = 32 uint4 per node
__device__ float4 g_h2v   [N_NODES * 64];   // 256 fp32  = 64 float4 per node
__device__ float4 g_el1v  [N_NODES];        // 4 heads
__device__ float4 g_er1v  [N_NODES];
__device__ float  g_feat2 [N_NODES * OUTP];
__device__ float  g_el2   [N_NODES];
__device__ float  g_er2   [N_NODES];

__device__ int   g_deg   [N_NODES];
__device__ int   g_rowptr[N_NODES + 1];
__device__ int   g_cursor[N_NODES];
__device__ int   g_esrc  [N_EDGES];

__device__ __forceinline__ float tf32r(float x) {
    uint32_t u;
    asm("cvt.rna.tf32.f32 %0, %1;" : "=r"(u) : "f"(x));
    return __uint_as_float(u);
}

// ---------------- init ----------------
__global__ void init_kernel() {
    int i = blockIdx.x * blockDim.x + threadIdx.x;
    if (i < N_NODES) { g_deg[i] = 0; g_cursor[i] = 0; }
}

// ---------------- CSR: count ----------------
__global__ void count_kernel(const int* __restrict__ dst, int E) {
    int e4 = (blockIdx.x * blockDim.x + threadIdx.x) * 4;
    if (e4 + 3 < E) {
        int4 d = *(const int4*)&dst[e4];
        atomicAdd(&g_deg[d.x], 1); atomicAdd(&g_deg[d.y], 1);
        atomicAdd(&g_deg[d.z], 1); atomicAdd(&g_deg[d.w], 1);
    } else {
        for (int e = e4; e < E; e++) atomicAdd(&g_deg[dst[e]], 1);
    }
}

// ---------------- CSR: scan ----------------
__global__ void scan_kernel() {
    __shared__ int part[1024];
    const int PER = (N_NODES + 1023) / 1024;   // 10
    int t = threadIdx.x;
    int base = t * PER;
    int loc[PER];
    int sum = 0;
#pragma unroll
    for (int i = 0; i < PER; i++) {
        int idx = base + i;
        int v = (idx < N_NODES) ? g_deg[idx] : 0;
        sum += v;
        loc[i] = sum;
    }
    part[t] = sum;
    __syncthreads();
    for (int off = 1; off < 1024; off <<= 1) {
        int add = (t >= off) ? part[t - off] : 0;
        __syncthreads();
        part[t] += add;
        __syncthreads();
    }
    int offset = (t > 0) ? part[t - 1] : 0;
#pragma unroll
    for (int i = 0; i < PER; i++) {
        int idx = base + i;
        if (idx < N_NODES) g_rowptr[idx + 1] = offset + loc[i];
    }
    if (t == 0) g_rowptr[0] = 0;
}

// ---------------- FUSED: gemm1(+attn dots, fp16 store) ∥ scatter ------------
// blocks [0, gx*NH)      : GEMM1 tile (bx = b % gx, head = b / gx)
// blocks [gx*NH, +sblk)  : CSR scatter (latency-bound; hides under GEMM)
__global__ void gemm1_scatter_kernel(const float* __restrict__ A,
                                     const float* __restrict__ B,
                                     const float* __restrict__ al,
                                     const float* __restrict__ ar,
                                     const int* __restrict__ src,
                                     const int* __restrict__ dst,
                                     int N, int E, int gx) {
    __shared__ float As[128][36];
    __shared__ float Bs[32][72];
    __shared__ float el_sh[128], er_sh[128];

    int b = blockIdx.x;
    int tid = threadIdx.x;

    if (b >= gx * NH) {
        // ---- scatter branch ----
        int sb = b - gx * NH;
        int e4 = (sb * blockDim.x + tid) * 4;
        if (e4 + 3 < E) {
            int4 s = *(const int4*)&src[e4];
            int4 d = *(const int4*)&dst[e4];
            g_esrc[g_rowptr[d.x] + atomicAdd(&g_cursor[d.x], 1)] = s.x;
            g_esrc[g_rowptr[d.y] + atomicAdd(&g_cursor[d.y], 1)] = s.y;
            g_esrc[g_rowptr[d.z] + atomicAdd(&g_cursor[d.z], 1)] = s.z;
            g_esrc[g_rowptr[d.w] + atomicAdd(&g_cursor[d.w], 1)] = s.w;
        } else {
            for (int e = e4; e < E; e++) {
                int d = dst[e];
                g_esrc[g_rowptr[d] + atomicAdd(&g_cursor[d], 1)] = src[e];
            }
        }
        return;
    }

    // ---- GEMM1 branch ----
    int wid  = tid >> 5, lane = tid & 31;
    int g    = lane >> 2, tig = lane & 3;
    int warpM = wid >> 1, warpN = wid & 1;
    int h    = b / gx;
    int row0 = (b % gx) * 128, col0 = h * 64;

    __half2* f1h = reinterpret_cast<__half2*>(g_feat1v);
    float*   el1 = reinterpret_cast<float*>(g_el1v);
    float*   er1 = reinterpret_cast<float*>(g_er1v);

    if (tid < 128) { el_sh[tid] = 0.f; er_sh[tid] = 0.f; }

    float c[2][4][4];
#pragma unroll
    for (int mf = 0; mf < 2; mf++)
#pragma unroll
        for (int nf = 0; nf < 4; nf++)
#pragma unroll
            for (int j = 0; j < 4; j++) c[mf][nf][j] = 0.f;

    for (int kk = 0; kk < IN_F; kk += 32) {
#pragma unroll
        for (int i = 0; i < 4; i++) {
            int idx = tid + i * 256;
            int m = idx >> 3, kq = (idx & 7) * 4;
            int r = row0 + m;
            float4 v = (r < N) ? *(const float4*)&A[r * IN_F + kk + kq]
                               : make_float4(0.f, 0.f, 0.f, 0.f);
            As[m][kq + 0] = tf32r(v.x); As[m][kq + 1] = tf32r(v.y);
            As[m][kq + 2] = tf32r(v.z); As[m][kq + 3] = tf32r(v.w);
        }
#pragma unroll
        for (int i = 0; i < 2; i++) {
            int idx = tid + i * 256;
            int k = idx >> 4, nq = (idx & 15) * 4;
            float4 v = *(const float4*)&B[(kk + k) * HD + col0 + nq];
            Bs[k][nq + 0] = tf32r(v.x); Bs[k][nq + 1] = tf32r(v.y);
            Bs[k][nq + 2] = tf32r(v.z); Bs[k][nq + 3] = tf32r(v.w);
        }
        __syncthreads();

#pragma unroll
        for (int ks = 0; ks < 32; ks += 8) {
            uint32_t af[2][4], bf[4][2];
#pragma unroll
            for (int mf = 0; mf < 2; mf++) {
                int mbase = warpM * 32 + mf * 16;
                af[mf][0] = __float_as_uint(As[mbase + g    ][ks + tig    ]);
                af[mf][1] = __float_as_uint(As[mbase + g + 8][ks + tig    ]);
                af[mf][2] = __float_as_uint(As[mbase + g    ][ks + tig + 4]);
                af[mf][3] = __float_as_uint(As[mbase + g + 8][ks + tig + 4]);
            }
#pragma unroll
            for (int nf = 0; nf < 4; nf++) {
                int nbase = warpN * 32 + nf * 8;
                bf[nf][0] = __float_as_uint(Bs[ks + tig    ][nbase + g]);
                bf[nf][1] = __float_as_uint(Bs[ks + tig + 4][nbase + g]);
            }
#pragma unroll
            for (int mf = 0; mf < 2; mf++)
#pragma unroll
                for (int nf = 0; nf < 4; nf++) {
                    asm volatile(
                        "mma.sync.aligned.m16n8k8.row.col.f32.tf32.tf32.f32 "
                        "{%0,%1,%2,%3}, {%4,%5,%6,%7}, {%8,%9}, {%0,%1,%2,%3};"
                        : "+f"(c[mf][nf][0]), "+f"(c[mf][nf][1]),
                          "+f"(c[mf][nf][2]), "+f"(c[mf][nf][3])
                        : "r"(af[mf][0]), "r"(af[mf][1]),
                          "r"(af[mf][2]), "r"(af[mf][3]),
                          "r"(bf[nf][0]), "r"(bf[nf][1]));
                }
        }
        __syncthreads();
    }

    float alv[4][2], arv[4][2];
#pragma unroll
    for (int nf = 0; nf < 4; nf++)
#pragma unroll
        for (int j = 0; j < 2; j++) {
            int col = warpN * 32 + nf * 8 + 2 * tig + j;
            alv[nf][j] = al[h * D1 + col];
            arv[nf][j] = ar[h * D1 + col];
        }

#pragma unroll
    for (int mf = 0; mf < 2; mf++) {
        int lr0 = warpM * 32 + mf * 16 + g;
        int lr1 = lr0 + 8;
        int r0g = row0 + lr0, r1g = row0 + lr1;
        float el0 = 0.f, er0 = 0.f, el1v = 0.f, er1v = 0.f;
#pragma unroll
        for (int nf = 0; nf < 4; nf++) {
            int colw = warpN * 32 + nf * 8 + 2 * tig;
            int cp = (col0 + colw) >> 1;
            if (r0g < N)
                f1h[r0g * (HD/2) + cp] = __floats2half2_rn(c[mf][nf][0], c[mf][nf][1]);
            if (r1g < N)
                f1h[r1g * (HD/2) + cp] = __floats2half2_rn(c[mf][nf][2], c[mf][nf][3]);
            el0 += c[mf][nf][0] * alv[nf][0] + c[mf][nf][1] * alv[nf][1];
            er0 += c[mf][nf][0] * arv[nf][0] + c[mf][nf][1] * arv[nf][1];
            el1v += c[mf][nf][2] * alv[nf][0] + c[mf][nf][3] * alv[nf][1];
            er1v += c[mf][nf][2] * arv[nf][0] + c[mf][nf][3] * arv[nf][1];
        }
#pragma unroll
        for (int o = 1; o < 4; o <<= 1) {
            el0  += __shfl_xor_sync(0xffffffffu, el0,  o, 4);
            er0  += __shfl_xor_sync(0xffffffffu, er0,  o, 4);
            el1v += __shfl_xor_sync(0xffffffffu, el1v, o, 4);
            er1v += __shfl_xor_sync(0xffffffffu, er1v, o, 4);
        }
        if (tig == 0) {
            atomicAdd(&el_sh[lr0], el0);  atomicAdd(&er_sh[lr0], er0);
            atomicAdd(&el_sh[lr1], el1v); atomicAdd(&er_sh[lr1], er1v);
        }
    }
    __syncthreads();
    if (tid < 128) {
        int r = row0 + tid;
        if (r < N) {
            el1[r * NH + h] = el_sh[tid];
            er1[r * NH + h] = er_sh[tid];
        }
    }
}

// ---------------- layer1: softmax + agg + elu; warp-autonomous --------------
// 8 nodes/block, warp per node, per-warp smem staging, __syncwarp only.
__global__ void sfm_agg1_kernel(int N) {
    __shared__ int   s_sh[8][32];
    __shared__ float w_sh[8][NH][32];

    int tid = threadIdx.x;
    int wid = tid >> 5, lane = tid & 31;
    int n = blockIdx.x * 8 + wid;
    if (n >= N) return;                       // uniform per warp

    int r0 = g_rowptr[n];
    int deg = g_rowptr[n + 1] - r0;
    float4 ern4 = g_er1v[n];

    float mx[NH] = {-INFINITY, -INFINITY, -INFINITY, -INFINITY};
    for (int i = lane; i < deg; i += 32) {
        int s = g_esrc[r0 + i];
        float4 el4 = g_el1v[s];
        float x0 = el4.x + ern4.x; x0 = (x0 > 0.f) ? x0 : NEG * x0;
        float x1 = el4.y + ern4.y; x1 = (x1 > 0.f) ? x1 : NEG * x1;
        float x2 = el4.z + ern4.z; x2 = (x2 > 0.f) ? x2 : NEG * x2;
        float x3 = el4.w + ern4.w; x3 = (x3 > 0.f) ? x3 : NEG * x3;
        mx[0] = fmaxf(mx[0], x0); mx[1] = fmaxf(mx[1], x1);
        mx[2] = fmaxf(mx[2], x2); mx[3] = fmaxf(mx[3], x3);
    }
#pragma unroll
    for (int h = 0; h < NH; h++)
#pragma unroll
        for (int o = 16; o; o >>= 1)
            mx[h] = fmaxf(mx[h], __shfl_xor_sync(0xffffffffu, mx[h], o));

    float den[NH] = {0.f, 0.f, 0.f, 0.f};
    for (int i = lane; i < deg; i += 32) {
        int s = g_esrc[r0 + i];
        float4 el4 = g_el1v[s];
        float x0 = el4.x + ern4.x; x0 = (x0 > 0.f) ? x0 : NEG * x0;
        float x1 = el4.y + ern4.y; x1 = (x1 > 0.f) ? x1 : NEG * x1;
        float x2 = el4.z + ern4.z; x2 = (x2 > 0.f) ? x2 : NEG * x2;
        float x3 = el4.w + ern4.w; x3 = (x3 > 0.f) ? x3 : NEG * x3;
        den[0] += __expf(x0 - mx[0]); den[1] += __expf(x1 - mx[1]);
        den[2] += __expf(x2 - mx[2]); den[3] += __expf(x3 - mx[3]);
    }
#pragma unroll
    for (int h = 0; h < NH; h++)
#pragma unroll
        for (int o = 16; o; o >>= 1)
            den[h] += __shfl_xor_sync(0xffffffffu, den[h], o);

    float idw[NH];
#pragma unroll
    for (int h = 0; h < NH; h++) idw[h] = 1.f / fmaxf(den[h], 1e-9f);

    int hme = lane >> 3;
    float acc[8] = {};

    for (int i0 = 0; i0 < deg; i0 += 32) {
        int cnt = min(32, deg - i0);          // uniform per warp
        if (lane < cnt) {
            int s = g_esrc[r0 + i0 + lane];
            s_sh[wid][lane] = s;
            float4 el4 = g_el1v[s];
            float x0 = el4.x + ern4.x; x0 = (x0 > 0.f) ? x0 : NEG * x0;
            float x1 = el4.y + ern4.y; x1 = (x1 > 0.f) ? x1 : NEG * x1;
            float x2 = el4.z + ern4.z; x2 = (x2 > 0.f) ? x2 : NEG * x2;
            float x3 = el4.w + ern4.w; x3 = (x3 > 0.f) ? x3 : NEG * x3;
            w_sh[wid][0][lane] = __expf(x0 - mx[0]) * idw[0];
            w_sh[wid][1][lane] = __expf(x1 - mx[1]) * idw[1];
            w_sh[wid][2][lane] = __expf(x2 - mx[2]) * idw[2];
            w_sh[wid][3][lane] = __expf(x3 - mx[3]) * idw[3];
        }
        __syncwarp();
        for (int i = 0; i < cnt; i++) {
            int s = s_sh[wid][i];
            float w = w_sh[wid][hme][i];
            uint4 raw = g_feat1v[s * 32 + lane];       // 8 fp16 channels
            float2 p0 = __half22float2(*reinterpret_cast<__half2*>(&raw.x));
            float2 p1 = __half22float2(*reinterpret_cast<__half2*>(&raw.y));
            float2 p2 = __half22float2(*reinterpret_cast<__half2*>(&raw.z));
            float2 p3 = __half22float2(*reinterpret_cast<__half2*>(&raw.w));
            acc[0] += w * p0.x; acc[1] += w * p0.y;
            acc[2] += w * p1.x; acc[3] += w * p1.y;
            acc[4] += w * p2.x; acc[5] += w * p2.y;
            acc[6] += w * p3.x; acc[7] += w * p3.y;
        }
        __syncwarp();
    }

    float o[8];
#pragma unroll
    for (int q = 0; q < 8; q++)
        o[q] = (acc[q] > 0.f) ? acc[q] : expm1f(acc[q]);
    g_h2v[n * 64 + lane * 2]     = make_float4(o[0], o[1], o[2], o[3]);
    g_h2v[n * 64 + lane * 2 + 1] = make_float4(o[4], o[5], o[6], o[7]);
}

// ---------------- layer2 GEMM (tf32 mma) + attention dots -------------------
__global__ void gemm2_attn_kernel(const float* __restrict__ W2,
                                  const float* __restrict__ al2,
                                  const float* __restrict__ ar2, int N) {
    __shared__ float As[128][36];
    __shared__ float Bs[32][72];
    __shared__ float el_sh[128], er_sh[128];

    int tid  = threadIdx.x;
    int wid  = tid >> 5, lane = tid & 31;
    int g    = lane >> 2, tig = lane & 3;
    int warpM = wid >> 1, warpN = wid & 1;
    int row0 = blockIdx.x * 128;

    if (tid < 128) { el_sh[tid] = 0.f; er_sh[tid] = 0.f; }

    float c[2][4][4];
#pragma unroll
    for (int mf = 0; mf < 2; mf++)
#pragma unroll
        for (int nf = 0; nf < 4; nf++)
#pragma unroll
            for (int j = 0; j < 4; j++) c[mf][nf][j] = 0.f;

    for (int kk = 0; kk < HD; kk += 32) {
#pragma unroll
        for (int i = 0; i < 4; i++) {
            int idx = tid + i * 256;
            int m = idx >> 3, kq = (idx & 7) * 4;
            int r = row0 + m;
            float4 v = (r < N) ? g_h2v[r * 64 + (kk + kq) / 4]
                               : make_float4(0.f, 0.f, 0.f, 0.f);
            As[m][kq + 0] = tf32r(v.x); As[m][kq + 1] = tf32r(v.y);
            As[m][kq + 2] = tf32r(v.z); As[m][kq + 3] = tf32r(v.w);
        }
#pragma unroll
        for (int i = 0; i < 8; i++) {
            int idx = tid + i * 256;
            int k = idx >> 6, nn = idx & 63;
            Bs[k][nn] = (nn < OUTF) ? tf32r(W2[(kk + k) * OUTF + nn]) : 0.f;
        }
        __syncthreads();

#pragma unroll
        for (int ks = 0; ks < 32; ks += 8) {
            uint32_t af[2][4], bf[4][2];
#pragma unroll
            for (int mf = 0; mf < 2; mf++) {
                int mbase = warpM * 32 + mf * 16;
                af[mf][0] = __float_as_uint(As[mbase + g    ][ks + tig    ]);
                af[mf][1] = __float_as_uint(As[mbase + g + 8][ks + tig    ]);
                af[mf][2] = __float_as_uint(As[mbase + g    ][ks + tig + 4]);
                af[mf][3] = __float_as_uint(As[mbase + g + 8][ks + tig + 4]);
            }
#pragma unroll
            for (int nf = 0; nf < 4; nf++) {
                int nbase = warpN * 32 + nf * 8;
                bf[nf][0] = __float_as_uint(Bs[ks + tig    ][nbase + g]);
                bf[nf][1] = __float_as_uint(Bs[ks + tig + 4][nbase + g]);
            }
#pragma unroll
            for (int mf = 0; mf < 2; mf++)
#pragma unroll
                for (int nf = 0; nf < 4; nf++) {
                    asm volatile(
                        "mma.sync.aligned.m16n8k8.row.col.f32.tf32.tf32.f32 "
                        "{%0,%1,%2,%3}, {%4,%5,%6,%7}, {%8,%9}, {%0,%1,%2,%3};"
                        : "+f"(c[mf][nf][0]), "+f"(c[mf][nf][1]),
                          "+f"(c[mf][nf][2]), "+f"(c[mf][nf][3])
                        : "r"(af[mf][0]), "r"(af[mf][1]),
                          "r"(af[mf][2]), "r"(af[mf][3]),
                          "r"(bf[nf][0]), "r"(bf[nf][1]));
                }
        }
        __syncthreads();
    }

    float alv[4][2], arv[4][2];
#pragma unroll
    for (int nf = 0; nf < 4; nf++)
#pragma unroll
        for (int j = 0; j < 2; j++) {
            int col = warpN * 32 + nf * 8 + 2 * tig + j;
            alv[nf][j] = (col < OUTF) ? al2[col] : 0.f;
            arv[nf][j] = (col < OUTF) ? ar2[col] : 0.f;
        }

#pragma unroll
    for (int mf = 0; mf < 2; mf++) {
        int lr0 = warpM * 32 + mf * 16 + g;
        int lr1 = lr0 + 8;
        int r0g = row0 + lr0, r1g = row0 + lr1;
        float el0 = 0.f, er0 = 0.f, el1v = 0.f, er1v = 0.f;
#pragma unroll
        for (int nf = 0; nf < 4; nf++) {
            int colw = warpN * 32 + nf * 8 + 2 * tig;
#pragma unroll
            for (int j = 0; j < 2; j++) {
                int col = colw + j;
                if (col < OUTF) {
                    if (r0g < N) g_feat2[r0g * OUTP + col] = c[mf][nf][j];
                    if (r1g < N) g_feat2[r1g * OUTP + col] = c[mf][nf][2 + j];
                }
            }
            el0 += c[mf][nf][0] * alv[nf][0] + c[mf][nf][1] * alv[nf][1];
            er0 += c[mf][nf][0] * arv[nf][0] + c[mf][nf][1] * arv[nf][1];
            el1v += c[mf][nf][2] * alv[nf][0] + c[mf][nf][3] * alv[nf][1];
            er1v += c[mf][nf][2] * arv[nf][0] + c[mf][nf][3] * arv[nf][1];
        }
#pragma unroll
        for (int o = 1; o < 4; o <<= 1) {
            el0  += __shfl_xor_sync(0xffffffffu, el0,  o, 4);
            er0  += __shfl_xor_sync(0xffffffffu, er0,  o, 4);
            el1v += __shfl_xor_sync(0xffffffffu, el1v, o, 4);
            er1v += __shfl_xor_sync(0xffffffffu, er1v, o, 4);
        }
        if (tig == 0) {
            atomicAdd(&el_sh[lr0], el0);  atomicAdd(&er_sh[lr0], er0);
            atomicAdd(&el_sh[lr1], el1v); atomicAdd(&er_sh[lr1], er1v);
        }
    }
    __syncthreads();
    if (tid < 128) {
        int r = row0 + tid;
        if (r < N) {
            g_el2[r] = el_sh[tid];
            g_er2[r] = er_sh[tid];
        }
    }
}

// ---------------- layer2: softmax + agg + log_softmax (warp per node) -------
__global__ void agg2_ls_kernel(float* __restrict__ out, int N) {
    int warp = threadIdx.x >> 5;
    int lane = threadIdx.x & 31;
    int n = blockIdx.x * 4 + warp;
    if (n >= N) return;
    int r0 = g_rowptr[n];
    int deg = g_rowptr[n + 1] - r0;
    float ern = g_er2[n];

    float mx = -INFINITY;
    for (int i = lane; i < deg; i += 32) {
        int s = g_esrc[r0 + i];
        float x = g_el2[s] + ern;
        x = (x > 0.f) ? x : NEG * x;
        mx = fmaxf(mx, x);
    }
#pragma unroll
    for (int o = 16; o; o >>= 1)
        mx = fmaxf(mx, __shfl_xor_sync(0xffffffffu, mx, o));

    float den = 0.f;
    for (int i = lane; i < deg; i += 32) {
        int s = g_esrc[r0 + i];
        float x = g_el2[s] + ern;
        x = (x > 0.f) ? x : NEG * x;
        den += __expf(x - mx);
    }
#pragma unroll
    for (int o = 16; o; o >>= 1)
        den += __shfl_xor_sync(0xffffffffu, den, o);
    den = fmaxf(den, 1e-9f);

    bool hi = (lane + 32) < OUTF;
    float a0 = 0.f, a1 = 0.f;
    for (int i = 0; i < deg; i++) {
        int s = g_esrc[r0 + i];
        float x = g_el2[s] + ern;
        x = (x > 0.f) ? x : NEG * x;
        float w = __expf(x - mx);
        a0 += w * g_feat2[s * OUTP + lane];
        if (hi) a1 += w * g_feat2[s * OUTP + lane + 32];
    }
    a0 /= den;
    a1 /= den;

    float v0 = a0;
    float v1 = hi ? a1 : -INFINITY;
    float m2 = fmaxf(v0, v1);
#pragma unroll
    for (int o = 16; o; o >>= 1)
        m2 = fmaxf(m2, __shfl_xor_sync(0xffffffffu, m2, o));
    float s_ = expf(v0 - m2) + (hi ? expf(v1 - m2) : 0.f);
#pragma unroll
    for (int o = 16; o; o >>= 1)
        s_ += __shfl_xor_sync(0xffffffffu, s_, o);
    float ls = logf(s_) + m2;
    out[n * OUTF + lane] = v0 - ls;
    if (hi) out[n * OUTF + lane + 32] = v1 - ls;
}

// ---------------- launch ----------------
extern "C" void kernel_launch(void* const* d_in, const int* in_sizes, int n_in,
                              void* d_out, int out_size) {
    const float* features = (const float*)d_in[0];
    const int*   src      = (const int*)d_in[1];
    const int*   dst      = (const int*)d_in[2];
    const float* W1       = (const float*)d_in[3];
    const float* al1      = (const float*)d_in[4];
    const float* ar1      = (const float*)d_in[5];
    const float* W2       = (const float*)d_in[6];
    const float* al2      = (const float*)d_in[7];
    const float* ar2      = (const float*)d_in[8];
    float* out = (float*)d_out;

    int N = in_sizes[0] / IN_F;   // 10000
    int E = in_sizes[1];          // 320000
    if (N > N_NODES) N = N_NODES;
    if (E > N_EDGES) E = N_EDGES;

    init_kernel<<<(N_NODES + 511) / 512, 512>>>();
    int e4blocks = (E / 4 + 255) / 256 + 1;
    count_kernel<<<e4blocks, 256>>>(dst, E);
    scan_kernel<<<1, 1024>>>();

    // fused: gemm1 tiles + scatter blocks in one launch (independent work)
    int gx = (N + 127) / 128;
    gemm1_scatter_kernel<<<gx * NH + e4blocks, 256>>>(
        features, W1, al1, ar1, src, dst, N, E, gx);

    sfm_agg1_kernel<<<(N + 7) / 8, 256>>>(N);
    gemm2_attn_kernel<<<(N + 127) / 128, 256>>>(W2, al2, ar2, N);
    agg2_ls_kernel<<<(N + 3) / 4, 128>>>(out, N);
}